// round 12
// baseline (speedup 1.0000x reference)
#include <cuda_runtime.h>
#include <cuda_bf16.h>
#include <math.h>
#include <stdint.h>

// Problem dims
#define BB   32
#define LL   1024
#define DD   512
#define HH   512
#define G4   2048
#define FF   256
#define OUTD 100
#define NCTA_LSTM 128
#define WIN  64          // exact softmax window; beyond this exp(score*decay - m) == exp(-m) in fp32

// ---------------- scratch (device globals; no allocation) ----------------
__device__ float g_pre  [BB * LL * G4];     // gates pre-activation, PERMUTED: [b][t][j*4+gate]
__device__ float g_cpart[BB * G4];          // concept part + biases (original gate order)
__device__ float g_hout [BB * LL * HH];     // LSTM hidden states
__device__ __nv_bfloat16 g_hbufb[4 * 2 * 2 * 8 * 512];  // [group][buf][hi/lo][batch][dim]
__device__ float g_mlp  [BB * LL * DD];     // mlp_out
__device__ float g_P    [BB * LL * HH];     // cumsum of hout over t
__device__ float g_csum [BB * 16 * HH];     // per-chunk sums for blocked scan
__device__ float g_wgt  [BB * LL * HH];     // attention output
__device__ float g_h1   [BB * LL * FF];     // relu(W1 ...)
__device__ unsigned g_flags[NCTA_LSTM * 32]; // per-CTA step flags, 128B apart

// bf16 hi|lo split operands (stride 1024: cols 0..511 = hi, 512..1023 = lo)
__device__ __nv_bfloat16 g_xs  [BB * LL * 1024];
__device__ __nv_bfloat16 g_wgts[BB * LL * 1024];
__device__ __nv_bfloat16 g_wihs[G4 * 1024];
__device__ __nv_bfloat16 g_wms [DD * 1024];
__device__ __nv_bfloat16 g_w1s [FF * 1024];

// ---------------- PTX helpers ----------------
__device__ __forceinline__ unsigned ld_acq(const unsigned* p) {
    unsigned v;
    asm volatile("ld.acquire.gpu.global.u32 %0, [%1];" : "=r"(v) : "l"(p));
    return v;
}
__device__ __forceinline__ void st_rel(unsigned* p, unsigned v) {
    asm volatile("st.release.gpu.global.u32 [%0], %1;" :: "l"(p), "r"(v));
}
__device__ __forceinline__ uint32_t s2u(const void* p) {
    uint32_t a;
    asm("{ .reg .u64 t; cvta.to.shared.u64 t, %1; cvt.u32.u64 %0, t; }" : "=r"(a) : "l"(p));
    return a;
}
__device__ __forceinline__ void ldm_x4(uint32_t* r, uint32_t addr) {
    asm volatile("ldmatrix.sync.aligned.m8n8.x4.shared.b16 {%0,%1,%2,%3}, [%4];"
                 : "=r"(r[0]), "=r"(r[1]), "=r"(r[2]), "=r"(r[3]) : "r"(addr));
}
__device__ __forceinline__ void mma16816(float* d, const uint32_t* a, uint32_t b0, uint32_t b1) {
    asm volatile("mma.sync.aligned.m16n8k16.row.col.f32.bf16.bf16.f32 "
                 "{%0,%1,%2,%3}, {%4,%5,%6,%7}, {%8,%9}, {%0,%1,%2,%3};"
                 : "+f"(d[0]), "+f"(d[1]), "+f"(d[2]), "+f"(d[3])
                 : "r"(a[0]), "r"(a[1]), "r"(a[2]), "r"(a[3]), "r"(b0), "r"(b1));
}

// ---------------- init ----------------
__global__ void k_init() {
    int i = blockIdx.x * 256 + threadIdx.x;
    if (i < 4 * 2 * 2 * 8 * 512) g_hbufb[i] = __float2bfloat16(0.0f);
    if (i < NCTA_LSTM * 32) g_flags[i] = 0u;
}

// ---------------- fp32 -> bf16 hi|lo split; dst stride 1024, 512-col source block ----
__global__ void k_split(const float* __restrict__ s, int ld, __nv_bfloat16* __restrict__ d) {
    long i = ((long)blockIdx.x * 256 + threadIdx.x) * 4;
    int r = (int)(i >> 9), c = (int)(i & 511);
    float4 v = *(const float4*)(s + (long)r * ld + c);
    float vv[4] = {v.x, v.y, v.z, v.w};
    __nv_bfloat16 h[4], l[4];
#pragma unroll
    for (int j = 0; j < 4; j++) {
        h[j] = __float2bfloat16(vv[j]);
        l[j] = __float2bfloat16(vv[j] - __bfloat162float(h[j]));
    }
    __nv_bfloat16* dh = d + (long)r * 1024 + c;
    *(__nv_bfloat162*)(dh)       = __nv_bfloat162(h[0], h[1]);
    *(__nv_bfloat162*)(dh + 2)   = __nv_bfloat162(h[2], h[3]);
    *(__nv_bfloat162*)(dh + 512) = __nv_bfloat162(l[0], l[1]);
    *(__nv_bfloat162*)(dh + 514) = __nv_bfloat162(l[2], l[3]);
}

// ---------------- cpart[b][g] = emb[concepts[b]] . Wih[g][512:1024] + bih[g] + bhh[g] --------
__global__ void k_cpart(const float* __restrict__ emb, const int* __restrict__ concepts,
                        const float* __restrict__ Wih, const float* __restrict__ bih,
                        const float* __restrict__ bhh) {
    int b = blockIdx.x >> 3;
    int g = ((blockIdx.x & 7) << 8) + threadIdx.x;
    const float4* e = (const float4*)(emb + (long)concepts[b] * HH);
    const float4* w = (const float4*)(Wih + (long)g * (2 * DD) + DD);
    float acc = bih[g] + bhh[g];
#pragma unroll 4
    for (int k = 0; k < HH / 4; k++) {
        float4 wv = __ldg(w + k);
        float4 ev = __ldg(e + k);
        acc += wv.x * ev.x + wv.y * ev.y + wv.z * ev.z + wv.w * ev.w;
    }
    g_cpart[b * G4 + g] = acc;
}

// ---------------- bf16-split tensor-core GEMM (mma.sync m16n8k16) ----------------
template<int RELU, int PERM>
__global__ void __launch_bounds__(256, 2)
k_mma(const __nv_bfloat16* __restrict__ A, const __nv_bfloat16* __restrict__ B,
      const float* __restrict__ bias, const float* __restrict__ rowvec,
      float* __restrict__ C, int ldc, int N) {
    __shared__ __nv_bfloat16 sA[128 * 72];
    __shared__ __nv_bfloat16 sB[128 * 72];
    int tid = threadIdx.x, wid = tid >> 5, lane = tid & 31;
    int wm = (wid >> 2) * 64, wn = (wid & 3) * 32;

    float d[4][4][4];
#pragma unroll
    for (int i = 0; i < 4; i++)
#pragma unroll
        for (int j = 0; j < 4; j++)
#pragma unroll
            for (int q = 0; q < 4; q++) d[i][j][q] = 0.0f;

    uint32_t sAu = s2u(sA), sBu = s2u(sB);
    uint32_t aRow = (uint32_t)(((wm + (lane & 15)) * 72 + (lane >> 4) * 8) * 2);
    uint32_t bRow = (uint32_t)(((wn + (lane >> 4) * 8 + (lane & 7)) * 72 + ((lane >> 3) & 1) * 8) * 2);

    long abase = (long)(blockIdx.y * 128) * 1024;
    long bbase = (long)(blockIdx.x * 128) * 1024;

    for (int kc = 0; kc < 24; kc++) {
        int ao = (kc < 8) ? kc * 64 : (kc < 16) ? 512 + (kc - 8) * 64 : (kc - 16) * 64;
        int bo = (kc < 8) ? kc * 64 : (kc < 16) ? (kc - 8) * 64 : 512 + (kc - 16) * 64;
#pragma unroll
        for (int it = 0; it < 4; it++) {
            int idx = tid + it * 256;
            int r = idx >> 3, cc = (idx & 7) * 8;
            *(uint4*)(sA + r * 72 + cc) = *(const uint4*)(A + abase + (long)r * 1024 + ao + cc);
            *(uint4*)(sB + r * 72 + cc) = *(const uint4*)(B + bbase + (long)r * 1024 + bo + cc);
        }
        __syncthreads();
#pragma unroll
        for (int ks = 0; ks < 4; ks++) {
            uint32_t af[4][4], bq[4], bf[4][2];
#pragma unroll
            for (int mi = 0; mi < 4; mi++)
                ldm_x4(af[mi], sAu + aRow + (uint32_t)((mi * 16 * 72 + ks * 16) * 2));
#pragma unroll
            for (int p = 0; p < 2; p++) {
                ldm_x4(bq, sBu + bRow + (uint32_t)((p * 16 * 72 + ks * 16) * 2));
                bf[p * 2][0]     = bq[0]; bf[p * 2][1]     = bq[1];
                bf[p * 2 + 1][0] = bq[2]; bf[p * 2 + 1][1] = bq[3];
            }
#pragma unroll
            for (int mi = 0; mi < 4; mi++)
#pragma unroll
                for (int nj = 0; nj < 4; nj++)
                    mma16816(d[mi][nj], af[mi], bf[nj][0], bf[nj][1]);
        }
        __syncthreads();
    }

    int g = lane >> 2, t2 = (lane & 3) * 2;
#pragma unroll
    for (int mi = 0; mi < 4; mi++) {
#pragma unroll
        for (int half = 0; half < 2; half++) {
            int mg = blockIdx.y * 128 + wm + mi * 16 + g + half * 8;
            const float* rv = rowvec ? (rowvec + (long)(mg >> 10) * N) : nullptr;
            float* crow = C + (long)mg * ldc;
#pragma unroll
            for (int nj = 0; nj < 4; nj++) {
                int n = blockIdx.x * 128 + wn + nj * 8 + t2;
                float v0 = d[mi][nj][half * 2];
                float v1 = d[mi][nj][half * 2 + 1];
                if (bias) { v0 += bias[n]; v1 += bias[n + 1]; }
                if (rv)   { v0 += rv[n];   v1 += rv[n + 1]; }
                if (RELU) { v0 = fmaxf(v0, 0.0f); v1 = fmaxf(v1, 0.0f); }
                if (PERM) {
                    crow[(((n)     & 511) << 2) | ((n)     >> 9)] = v0;
                    crow[(((n + 1) & 511) << 2) | ((n + 1) >> 9)] = v1;
                } else {
                    *(float2*)(crow + n) = make_float2(v0, v1);
                }
            }
        }
    }
}

// ---------------- scalar SGEMM (FF2 only: N=100, K=256) ----------------
template<bool RELU>
__global__ void k_gemm(const float* __restrict__ A, int lda,
                       const float* __restrict__ W, int ldw,
                       const float* __restrict__ bias,
                       float* __restrict__ C, int ldc,
                       int N, int K) {
    __shared__ float As[16 * 132];
    __shared__ float Bs[16 * 132];
    int tid = threadIdx.x;
    int bx = blockIdx.x, by = blockIdx.y;
    int tx = tid & 15, ty = tid >> 4;

    float acc[8][8];
#pragma unroll
    for (int i = 0; i < 8; i++)
#pragma unroll
        for (int j = 0; j < 8; j++) acc[i][j] = 0.0f;

    int row = tid >> 2;
    int kl  = (tid & 3) * 4;
    const float* Abase = A + (long)(by * 128 + row) * lda + kl;
    int n0l = bx * 128 + row, n1l = n0l + 64;
    const float* W0 = (n0l < N) ? (W + (long)n0l * ldw + kl) : nullptr;
    const float* W1 = (n1l < N) ? (W + (long)n1l * ldw + kl) : nullptr;

    for (int kt = 0; kt < K; kt += 16) {
        float4 a0 = *(const float4*)(Abase + kt);
        float4 a1 = *(const float4*)(Abase + kt + (long)64 * lda);
        float4 b0 = make_float4(0.f, 0.f, 0.f, 0.f);
        float4 b1 = make_float4(0.f, 0.f, 0.f, 0.f);
        if (W0) b0 = *(const float4*)(W0 + kt);
        if (W1) b1 = *(const float4*)(W1 + kt);
#pragma unroll
        for (int q = 0; q < 4; q++) {
            float av0 = q == 0 ? a0.x : q == 1 ? a0.y : q == 2 ? a0.z : a0.w;
            float av1 = q == 0 ? a1.x : q == 1 ? a1.y : q == 2 ? a1.z : a1.w;
            float bv0 = q == 0 ? b0.x : q == 1 ? b0.y : q == 2 ? b0.z : b0.w;
            float bv1 = q == 0 ? b1.x : q == 1 ? b1.y : q == 2 ? b1.z : b1.w;
            As[(kl + q) * 132 + row]      = av0;
            As[(kl + q) * 132 + row + 64] = av1;
            Bs[(kl + q) * 132 + row]      = bv0;
            Bs[(kl + q) * 132 + row + 64] = bv1;
        }
        __syncthreads();
#pragma unroll
        for (int k = 0; k < 16; k++) {
            float4 av0 = *(const float4*)&As[k * 132 + ty * 8];
            float4 av1 = *(const float4*)&As[k * 132 + ty * 8 + 4];
            float4 bv0 = *(const float4*)&Bs[k * 132 + tx * 8];
            float4 bv1 = *(const float4*)&Bs[k * 132 + tx * 8 + 4];
            float a[8] = {av0.x, av0.y, av0.z, av0.w, av1.x, av1.y, av1.z, av1.w};
            float b[8] = {bv0.x, bv0.y, bv0.z, bv0.w, bv1.x, bv1.y, bv1.z, bv1.w};
#pragma unroll
            for (int i = 0; i < 8; i++)
#pragma unroll
                for (int j = 0; j < 8; j++) acc[i][j] += a[i] * b[j];
        }
        __syncthreads();
    }

    int m0 = by * 128 + ty * 8, nn0 = bx * 128 + tx * 8;
#pragma unroll
    for (int i = 0; i < 8; i++) {
        int m = m0 + i;
#pragma unroll
        for (int j = 0; j < 8; j++) {
            int n = nn0 + j;
            if (n < N) {
                float v = acc[i][j];
                if (bias) v += bias[n];
                if (RELU) v = fmaxf(v, 0.0f);
                C[(long)m * ldc + n] = v;
            }
        }
    }
}

// ---------------- persistent LSTM: 4 groups x 32 CTAs, mma.sync recurrent compute ----
// group = blockIdx.x>>5 owns batches [group*8,+8); gcta = blockIdx.x&31 owns hidden
// [gcta*16,+16) => 64 gate rows. Whh slice in smem as bf16 hi/lo [64][520].
// h published as bf16 hi/lo [batch][dim]; gates = Ah*Bh + Al*Bh + Ah*Bl via
// mma.m16n8k16 (M=16: 8 batches + zero pad). Warp w: gate rows [8w,8w+8), full K.
// No k-split reduction: mma yields complete gates -> 2KB smem -> fused activation.
__global__ void __launch_bounds__(256, 1)
k_lstm(const float* __restrict__ pre, const float* __restrict__ Whh) {
    extern __shared__ __nv_bfloat16 smb[];
    __nv_bfloat16* wh  = smb;                 // [64][520] weight hi
    __nv_bfloat16* wl  = smb + 64 * 520;      // [64][520] weight lo
    __nv_bfloat16* ahh = smb + 128 * 520;     // [16][520] h hi (rows 8..15 zero pad)
    __nv_bfloat16* ahl = smb + 144 * 520;     // [16][520] h lo
    float* gbuf = (float*)(smb + 160 * 520);  // [64][8] gates
    float* c_s  = gbuf + 512;                 // [128] cell state

    int tid   = threadIdx.x;
    int group = blockIdx.x >> 5;
    int gcta  = blockIdx.x & 31;
    int j0    = gcta * 16;
    int b0    = group * 8;
    int w     = tid >> 5;
    int lane  = tid & 31;

    // load Whh slice -> bf16 hi/lo: row lr -> grow = (lr>>4)*512 + j0 + (lr&15)
    for (int i = tid; i < 64 * 128; i += 256) {
        int lr = i >> 7, k4 = (i & 127) * 4;
        int grow = ((lr >> 4) << 9) + j0 + (lr & 15);
        float4 v = *(const float4*)(Whh + (long)grow * HH + k4);
        float vv[4] = {v.x, v.y, v.z, v.w};
#pragma unroll
        for (int q = 0; q < 4; q++) {
            __nv_bfloat16 hb = __float2bfloat16(vv[q]);
            wh[lr * 520 + k4 + q] = hb;
            wl[lr * 520 + k4 + q] = __float2bfloat16(vv[q] - __bfloat162float(hb));
        }
    }
    // zero A buffers entirely (pad rows/cols stay zero forever)
    for (int i = tid; i < 2 * 16 * 520 / 8; i += 256)
        *((uint4*)ahh + i) = make_uint4(0, 0, 0, 0);
    if (tid < 128) c_s[tid] = 0.0f;

    // act roles (tid < 128): hidden jl, batch ab
    int jl = tid >> 3, ab = tid & 7;
    long preoff = (long)(b0 + ab) * LL * G4 + (j0 + jl) * 4;

    // fragment addresses
    uint32_t whu = s2u(wh), ahhu = s2u(ahh);
    uint32_t aOff = (uint32_t)(((lane & 15) * 520 + (lane >> 4) * 8) * 2);
    uint32_t bOff = (uint32_t)(((8 * w + (lane & 7)) * 520 + (lane >> 3) * 8) * 2);

    // stage roles: warp w covers k range [64w, 64w+64); 128 (row,chunk) units
    __nv_bfloat16* hbg = g_hbufb + group * (2 * 2 * 8 * 512);
    unsigned* myflag = &g_flags[blockIdx.x * 32];
    const unsigned* pollflag = &g_flags[(group * 32 + w * 4 + (lane & 3)) * 32];

    __syncthreads();

    float4 pf4 = make_float4(0.f, 0.f, 0.f, 0.f);
    if (tid < 128) pf4 = *(const float4*)(pre + preoff);    // t = 0

    for (int t = 0; t < LL; t++) {
        // ---- per-warp: wait for 4 producers of dims [64w,64w+64), stage 2KB ----
        while (ld_acq(pollflag) < (unsigned)t) { }
        __syncwarp();
        {
            const __nv_bfloat16* src = hbg + (t & 1) * (2 * 8 * 512);
#pragma unroll
            for (int it = 0; it < 4; it++) {
                int idx = it * 32 + lane;       // 0..127
                int row = idx >> 3;             // 0..15: arr = row>>3, b = row&7
                int c   = idx & 7;
                int arr = row >> 3, b = row & 7;
                const uint4* s = (const uint4*)(src + arr * 4096 + b * 512 + 64 * w + c * 8);
                __nv_bfloat16* dsm = (arr ? ahl : ahh) + b * 520 + 64 * w + c * 8;
                *(uint4*)dsm = *s;
            }
        }
        __syncthreads();   // A ready (all k ranges)

        // ---- mma: 16 chunks of 32k; 6 ldmatrix + 6 mma per chunk; 4 acc sets ----
        float dq[4][4];
#pragma unroll
        for (int q = 0; q < 4; q++)
#pragma unroll
            for (int r = 0; r < 4; r++) dq[q][r] = 0.0f;

#pragma unroll 4
        for (int kc = 0; kc < 16; kc++) {
            uint32_t k0b = (uint32_t)(kc * 32 * 2);
            uint32_t a0[4], a1[4], a2[4], a3[4], bh[4], bl[4];
            ldm_x4(a0, ahhu + aOff + k0b);                       // hh k..k+16
            ldm_x4(a1, ahhu + aOff + k0b + 32);                  // hh k+16..k+32
            ldm_x4(a2, ahhu + 16 * 520 * 2 + aOff + k0b);        // hl k..k+16
            ldm_x4(a3, ahhu + 16 * 520 * 2 + aOff + k0b + 32);   // hl k+16..
            ldm_x4(bh, whu + bOff + k0b);                        // wh 4 k-tiles
            ldm_x4(bl, whu + 64 * 520 * 2 + bOff + k0b);         // wl
            float* dd = dq[kc & 3];
            mma16816(dd, a0, bh[0], bh[1]);
            mma16816(dd, a2, bh[0], bh[1]);
            mma16816(dd, a0, bl[0], bl[1]);
            mma16816(dd, a1, bh[2], bh[3]);
            mma16816(dd, a3, bh[2], bh[3]);
            mma16816(dd, a1, bl[2], bl[3]);
        }
        // c frag: c0/c1 at row = lane>>2 (batch), cols (lane&3)*2, +1
        {
            float c0 = dq[0][0] + dq[1][0] + dq[2][0] + dq[3][0];
            float c1 = dq[0][1] + dq[1][1] + dq[2][1] + dq[3][1];
            int brow = lane >> 2, bcol = (lane & 3) * 2;
            gbuf[(8 * w + bcol) * 8 + brow]     = c0;
            gbuf[(8 * w + bcol + 1) * 8 + brow] = c1;
        }
        __syncthreads();   // gates ready

        // ---- fused activation + publish (tid < 128) ----
        if (tid < 128) {
            float gi = gbuf[(jl)      * 8 + ab] + pf4.x;
            float gf = gbuf[(16 + jl) * 8 + ab] + pf4.y;
            float gg = gbuf[(32 + jl) * 8 + ab] + pf4.z;
            float go = gbuf[(48 + jl) * 8 + ab] + pf4.w;
            float si = __fdividef(1.0f, 1.0f + __expf(-gi));
            float sf = __fdividef(1.0f, 1.0f + __expf(-gf));
            float so = __fdividef(1.0f, 1.0f + __expf(-go));
            float ag = fabsf(gg);
            float eg = __expf(-2.0f * ag);
            float tg = copysignf(__fdividef(1.0f - eg, 1.0f + eg), gg);
            float c  = sf * c_s[tid] + si * tg;
            c_s[tid] = c;
            float ac = fabsf(c);
            float ec = __expf(-2.0f * ac);
            float tc = copysignf(__fdividef(1.0f - ec, 1.0f + ec), c);
            float h  = so * tc;
            // publish bf16 hi/lo for next step's recurrence
            __nv_bfloat16 hh = __float2bfloat16(h);
            __nv_bfloat16 hl = __float2bfloat16(h - __bfloat162float(hh));
            __nv_bfloat16* dst = hbg + ((t + 1) & 1) * (2 * 8 * 512);
            dst[ab * 512 + j0 + jl]        = hh;
            dst[4096 + ab * 512 + j0 + jl] = hl;
            g_hout[((long)(b0 + ab) * LL + t) * HH + j0 + jl] = h;
            if (t + 1 < LL)
                pf4 = *(const float4*)(pre + preoff + (long)(t + 1) * G4);
        }
        __syncthreads();
        if (tid == 0) st_rel(myflag, (unsigned)(t + 1));
    }
}

// ---------------- blocked cumsum ----------------
__global__ void k_csum1() {
    int c = blockIdx.x, b = blockIdx.y;
    int d = threadIdx.x;
    const float* s0 = g_hout + ((long)b * LL + c * 64) * HH + d;
    const float* s1 = s0 + 256;
    float* d0 = g_P + ((long)b * LL + c * 64) * HH + d;
    float* d1 = d0 + 256;
    float a0 = 0.f, a1 = 0.f;
#pragma unroll 8
    for (int t = 0; t < 64; t++) {
        a0 += s0[t * HH]; d0[t * HH] = a0;
        a1 += s1[t * HH]; d1[t * HH] = a1;
    }
    g_csum[((long)b * 16 + c) * HH + d]       = a0;
    g_csum[((long)b * 16 + c) * HH + d + 256] = a1;
}

__global__ void k_csum2() {
    int c = blockIdx.x + 1, b = blockIdx.y;
    int d = threadIdx.x;
    float o0 = 0.f, o1 = 0.f;
    for (int cc = 0; cc < c; cc++) {
        o0 += g_csum[((long)b * 16 + cc) * HH + d];
        o1 += g_csum[((long)b * 16 + cc) * HH + d + 256];
    }
    float* d0 = g_P + ((long)b * LL + c * 64) * HH + d;
    float* d1 = d0 + 256;
#pragma unroll 8
    for (int t = 0; t < 64; t++) {
        d0[t * HH] += o0;
        d1[t * HH] += o1;
    }
}

// ---------------- banded online-softmax attention ----------------
__device__ __forceinline__ void upd(float& m, float& l, float4* acc, float sc, const float4* ov) {
    if (sc <= m) {
        float e = __expf(sc - m);
        l += e;
#pragma unroll
        for (int j = 0; j < 4; j++) {
            acc[j].x += e * ov[j].x; acc[j].y += e * ov[j].y;
            acc[j].z += e * ov[j].z; acc[j].w += e * ov[j].w;
        }
    } else {
        float coef = __expf(m - sc);
        l = l * coef + 1.0f;
#pragma unroll
        for (int j = 0; j < 4; j++) {
            acc[j].x = acc[j].x * coef + ov[j].x; acc[j].y = acc[j].y * coef + ov[j].y;
            acc[j].z = acc[j].z * coef + ov[j].z; acc[j].w = acc[j].w * coef + ov[j].w;
        }
        m = sc;
    }
}

__global__ void k_attn() {
    int warp = (blockIdx.x * blockDim.x + threadIdx.x) >> 5;
    int lane = threadIdx.x & 31;
    int b  = warp >> 9;
    int tp = warp & 511;
    int t0 = tp * 2, t1 = t0 + 1;

    const float* mb = g_mlp  + (long)b * LL * DD;
    const float* ob = g_hout + (long)b * LL * HH;

    float4 q0[4], q1[4], acc0[4], acc1[4];
#pragma unroll
    for (int j = 0; j < 4; j++) {
        q0[j] = *(const float4*)(mb + (long)t0 * DD + lane * 4 + j * 128);
        q1[j] = *(const float4*)(mb + (long)t1 * DD + lane * 4 + j * 128);
        acc0[j] = make_float4(0.f, 0.f, 0.f, 0.f);
        acc1[j] = make_float4(0.f, 0.f, 0.f, 0.f);
    }
    float m0 = -1e30f, m1 = -1e30f, l0 = 0.0f, l1 = 0.0f;

    int slo = t0 - (WIN - 1); if (slo < 0) slo = 0;
    for (int s = slo; s <= t1; s++) {
        float4 ov[4];
        const float* op = ob + (long)s * HH + lane * 4;
#pragma unroll
        for (int j = 0; j < 4; j++) ov[j] = *(const float4*)(op + j * 128);
        float d0 = 0.f, d1 = 0.f;
#pragma unroll
        for (int j = 0; j < 4; j++) {
            d0 += q0[j].x * ov[j].x + q0[j].y * ov[j].y + q0[j].z * ov[j].z + q0[j].w * ov[j].w;
            d1 += q1[j].x * ov[j].x + q1[j].y * ov[j].y + q1[j].z * ov[j].z + q1[j].w * ov[j].w;
        }
#pragma unroll
        for (int off = 16; off; off >>= 1) {
            d0 += __shfl_xor_sync(0xFFFFFFFFu, d0, off);
            d1 += __shfl_xor_sync(0xFFFFFFFFu, d1, off);
        }
        if (s <= t0) {
            float sc = d0 * __expf(-0.6f * (float)(t0 - s));
            upd(m0, l0, acc0, sc, ov);
        }
        if (s >= t1 - (WIN - 1)) {
            float sc = d1 * __expf(-0.6f * (float)(t1 - s));
            upd(m1, l1, acc1, sc, ov);
        }
    }
    if (t0 >= WIN) {
        float cnt = (float)(t0 - (WIN - 1));
        const float* pp = g_P + ((long)b * LL + (t0 - WIN)) * HH + lane * 4;
        float4 pv[4];
#pragma unroll
        for (int j = 0; j < 4; j++) pv[j] = *(const float4*)(pp + j * 128);
        if (0.0f <= m0) {
            float e = __expf(-m0);
            l0 += cnt * e;
#pragma unroll
            for (int j = 0; j < 4; j++) {
                acc0[j].x += e * pv[j].x; acc0[j].y += e * pv[j].y;
                acc0[j].z += e * pv[j].z; acc0[j].w += e * pv[j].w;
            }
        } else {
            float coef = __expf(m0);
            l0 = l0 * coef + cnt;
#pragma unroll
            for (int j = 0; j < 4; j++) {
                acc0[j].x = acc0[j].x * coef + pv[j].x; acc0[j].y = acc0[j].y * coef + pv[j].y;
                acc0[j].z = acc0[j].z * coef + pv[j].z; acc0[j].w = acc0[j].w * coef + pv[j].w;
            }
            m0 = 0.0f;
        }
    }
    if (t1 >= WIN) {
        float cnt = (float)(t1 - (WIN - 1));
        const float* pp = g_P + ((long)b * LL + (t1 - WIN)) * HH + lane * 4;
        float4 pv[4];
#pragma unroll
        for (int j = 0; j < 4; j++) pv[j] = *(const float4*)(pp + j * 128);
        if (0.0f <= m1) {
            float e = __expf(-m1);
            l1 += cnt * e;
#pragma unroll
            for (int j = 0; j < 4; j++) {
                acc1[j].x += e * pv[j].x; acc1[j].y += e * pv[j].y;
                acc1[j].z += e * pv[j].z; acc1[j].w += e * pv[j].w;
            }
        } else {
            float coef = __expf(m1);
            l1 = l1 * coef + cnt;
#pragma unroll
            for (int j = 0; j < 4; j++) {
                acc1[j].x = acc1[j].x * coef + pv[j].x; acc1[j].y = acc1[j].y * coef + pv[j].y;
                acc1[j].z = acc1[j].z * coef + pv[j].z; acc1[j].w = acc1[j].w * coef + pv[j].w;
            }
            m1 = 0.0f;
        }
    }

    float inv0 = 1.0f / l0, inv1 = 1.0f / l1;
    float* w0 = g_wgt + ((long)b * LL + t0) * HH + lane * 4;
    float* w1 = g_wgt + ((long)b * LL + t1) * HH + lane * 4;
#pragma unroll
    for (int j = 0; j < 4; j++) {
        float4 r0 = make_float4(acc0[j].x * inv0, acc0[j].y * inv0, acc0[j].z * inv0, acc0[j].w * inv0);
        float4 r1 = make_float4(acc1[j].x * inv1, acc1[j].y * inv1, acc1[j].z * inv1, acc1[j].w * inv1);
        *(float4*)(w0 + j * 128) = r0;
        *(float4*)(w1 + j * 128) = r1;
    }
}

// ---------------- launch ----------------
extern "C" void kernel_launch(void* const* d_in, const int* in_sizes, int n_in,
                              void* d_out, int out_size) {
    const float* x        = (const float*)d_in[0];
    const int*   concepts = (const int*)  d_in[1];
    const float* emb      = (const float*)d_in[2];
    const float* Wih      = (const float*)d_in[3];
    const float* Whh      = (const float*)d_in[4];
    const float* bih      = (const float*)d_in[5];
    const float* bhh      = (const float*)d_in[6];
    const float* Wm       = (const float*)d_in[7];
    const float* bm       = (const float*)d_in[8];
    const float* W1       = (const float*)d_in[9];
    const float* b1       = (const float*)d_in[10];
    const float* W2       = (const float*)d_in[11];
    const float* b2       = (const float*)d_in[12];
    float* out = (float*)d_out;

    float *p_pre, *p_cpart, *p_mlp, *p_wgt, *p_h1;
    __nv_bfloat16 *p_xs, *p_wgts, *p_wihs, *p_wms, *p_w1s;
    cudaGetSymbolAddress((void**)&p_pre,   g_pre);
    cudaGetSymbolAddress((void**)&p_cpart, g_cpart);
    cudaGetSymbolAddress((void**)&p_mlp,   g_mlp);
    cudaGetSymbolAddress((void**)&p_wgt,   g_wgt);
    cudaGetSymbolAddress((void**)&p_h1,    g_h1);
    cudaGetSymbolAddress((void**)&p_xs,    g_xs);
    cudaGetSymbolAddress((void**)&p_wgts,  g_wgts);
    cudaGetSymbolAddress((void**)&p_wihs,  g_wihs);
    cudaGetSymbolAddress((void**)&p_wms,   g_wms);
    cudaGetSymbolAddress((void**)&p_w1s,   g_w1s);

    // smem: bf16[160*520] + gbuf 2KB + c_s 512B = ~169KB
    const int lstm_smem = 160 * 520 * 2 + (512 + 128) * 4;
    cudaFuncSetAttribute(k_lstm, cudaFuncAttributeMaxDynamicSharedMemorySize, lstm_smem);

    const int M = BB * LL;   // 32768

    k_init<<<256, 256>>>();
    k_cpart<<<BB * 8, 256>>>(emb, concepts, Wih, bih, bhh);

    // bf16 hi|lo splits
    k_split<<<(int)(((long)M * DD) / 1024), 256>>>(x,   DD,     p_xs);
    k_split<<<(G4 * DD) / 1024,             256>>>(Wih, 2 * DD, p_wihs);   // WihA cols 0..511
    k_split<<<(DD * DD) / 1024,             256>>>(Wm,  DD,     p_wms);
    k_split<<<(FF * HH) / 1024,             256>>>(W1,  HH,     p_w1s);

    // pre = x @ WihA^T + cpart (PERMUTED output) -- tensor core mma.sync
    k_mma<0, 1><<<dim3(G4 / 128, M / 128), 256>>>(p_xs, p_wihs, nullptr, p_cpart, p_pre, G4, G4);
    // mlp = x @ Wm^T + bm
    k_mma<0, 0><<<dim3(DD / 128, M / 128), 256>>>(p_xs, p_wms, bm, nullptr, p_mlp, DD, DD);

    // LSTM recurrence (4 groups x 32 CTAs, mma.sync compute)
    k_lstm<<<NCTA_LSTM, 256, lstm_smem>>>(p_pre, Whh);

    // blocked prefix sums
    k_csum1<<<dim3(16, BB), 256>>>();
    k_csum2<<<dim3(15, BB), 256>>>();

    // attention
    k_attn<<<2048, 256>>>();

    // h1 = relu(wgt @ W1^T + b1) -- tensor core (split wgt first)
    k_split<<<(int)(((long)M * HH) / 1024), 256>>>(p_wgt, HH, p_wgts);
    k_mma<1, 0><<<dim3(FF / 128, M / 128), 256>>>(p_wgts, p_w1s, b1, nullptr, p_h1, FF, FF);

    // res = h1 @ W2^T + b2 -- scalar (N=100)
    k_gemm<false><<<dim3(1, M / 128), 256>>>(p_h1, FF, W2, FF, b2, out, OUTD, OUTD, FF);
}

// round 13
// speedup vs baseline: 1.0166x; 1.0166x over previous
#include <cuda_runtime.h>
#include <cuda_bf16.h>
#include <math.h>
#include <stdint.h>

// Problem dims
#define BB   32
#define LL   1024
#define DD   512
#define HH   512
#define G4   2048
#define FF   256
#define OUTD 100
#define NCTA_LSTM 128
#define WIN  64          // exact softmax window; beyond this exp(score*decay - m) == exp(-m) in fp32

// ---------------- scratch (device globals; no allocation) ----------------
__device__ float g_pre  [BB * LL * G4];     // gates pre-activation, PERMUTED: [b][t][j*4+gate]
__device__ float g_cpart[BB * G4];          // concept part + biases (original gate order)
__device__ float g_hout [BB * LL * HH];     // LSTM hidden states
__device__ float g_hbuf [4 * 2 * HH * 8];   // per-group h double buffers [group][buf][k][8]
__device__ float g_mlp  [BB * LL * DD];     // mlp_out
__device__ float g_P    [BB * LL * HH];     // cumsum of hout over t
__device__ float g_csum [BB * 16 * HH];     // per-chunk sums for blocked scan
__device__ unsigned g_flags[NCTA_LSTM * 32]; // per-CTA step flags, 128B apart

// bf16 hi|lo split operands
__device__ __nv_bfloat16 g_xs  [BB * LL * 1024];   // x      [M][1024] (hi|lo, K=512)
__device__ __nv_bfloat16 g_wgts[BB * LL * 1024];   // wgt    (written by k_attn)
__device__ __nv_bfloat16 g_h1s [BB * LL * 512];    // h1     [M][512]  (hi|lo, K=256)
__device__ __nv_bfloat16 g_wihs[G4 * 1024];
__device__ __nv_bfloat16 g_wms [DD * 1024];
__device__ __nv_bfloat16 g_w1s [FF * 1024];
__device__ __nv_bfloat16 g_w2s [128 * 512];        // W2 padded to 128 rows (hi|lo, K=256)

// ---------------- PTX helpers ----------------
__device__ __forceinline__ unsigned long long pk2(float lo, float hi) {
    unsigned long long r;
    asm("mov.b64 %0, {%1, %2};" : "=l"(r) : "f"(lo), "f"(hi));
    return r;
}
__device__ __forceinline__ void ffma2(unsigned long long& d, unsigned long long a,
                                      unsigned long long b) {
    asm("fma.rn.f32x2 %0, %1, %2, %0;" : "+l"(d) : "l"(a), "l"(b));
}
__device__ __forceinline__ unsigned ld_acq(const unsigned* p) {
    unsigned v;
    asm volatile("ld.acquire.gpu.global.u32 %0, [%1];" : "=r"(v) : "l"(p));
    return v;
}
__device__ __forceinline__ void st_rel(unsigned* p, unsigned v) {
    asm volatile("st.release.gpu.global.u32 [%0], %1;" :: "l"(p), "r"(v));
}
__device__ __forceinline__ uint32_t s2u(const void* p) {
    uint32_t a;
    asm("{ .reg .u64 t; cvta.to.shared.u64 t, %1; cvt.u32.u64 %0, t; }" : "=r"(a) : "l"(p));
    return a;
}
__device__ __forceinline__ void ldm_x4(uint32_t* r, uint32_t addr) {
    asm volatile("ldmatrix.sync.aligned.m8n8.x4.shared.b16 {%0,%1,%2,%3}, [%4];"
                 : "=r"(r[0]), "=r"(r[1]), "=r"(r[2]), "=r"(r[3]) : "r"(addr));
}
__device__ __forceinline__ void mma16816(float* d, const uint32_t* a, uint32_t b0, uint32_t b1) {
    asm volatile("mma.sync.aligned.m16n8k16.row.col.f32.bf16.bf16.f32 "
                 "{%0,%1,%2,%3}, {%4,%5,%6,%7}, {%8,%9}, {%0,%1,%2,%3};"
                 : "+f"(d[0]), "+f"(d[1]), "+f"(d[2]), "+f"(d[3])
                 : "r"(a[0]), "r"(a[1]), "r"(a[2]), "r"(a[3]), "r"(b0), "r"(b1));
}
__device__ __forceinline__ __nv_bfloat162 splt2(float v0, float v1, __nv_bfloat162& lo) {
    __nv_bfloat16 h0 = __float2bfloat16(v0);
    __nv_bfloat16 h1 = __float2bfloat16(v1);
    lo = __nv_bfloat162(__float2bfloat16(v0 - __bfloat162float(h0)),
                        __float2bfloat16(v1 - __bfloat162float(h1)));
    return __nv_bfloat162(h0, h1);
}

// ---------------- init ----------------
__global__ void k_init() {
    int i = blockIdx.x * 256 + threadIdx.x;
    if (i < 4 * 2 * HH * 8) g_hbuf[i] = 0.0f;
    if (i < NCTA_LSTM * 32) g_flags[i] = 0u;
}

// ---------------- fp32 -> bf16 hi|lo split; dst stride 1024, 512-col source block ----
__global__ void k_split(const float* __restrict__ s, int ld, __nv_bfloat16* __restrict__ d) {
    long i = ((long)blockIdx.x * 256 + threadIdx.x) * 4;
    int r = (int)(i >> 9), c = (int)(i & 511);
    float4 v = *(const float4*)(s + (long)r * ld + c);
    float vv[4] = {v.x, v.y, v.z, v.w};
    __nv_bfloat16 h[4], l[4];
#pragma unroll
    for (int j = 0; j < 4; j++) {
        h[j] = __float2bfloat16(vv[j]);
        l[j] = __float2bfloat16(vv[j] - __bfloat162float(h[j]));
    }
    __nv_bfloat16* dh = d + (long)r * 1024 + c;
    *(__nv_bfloat162*)(dh)       = __nv_bfloat162(h[0], h[1]);
    *(__nv_bfloat162*)(dh + 2)   = __nv_bfloat162(h[2], h[3]);
    *(__nv_bfloat162*)(dh + 512) = __nv_bfloat162(l[0], l[1]);
    *(__nv_bfloat162*)(dh + 514) = __nv_bfloat162(l[2], l[3]);
}

// W2 [100][256] -> g_w2s [128][512] hi|lo, rows >= 100 zeroed
__global__ void k_splitw2(const float* __restrict__ W2) {
    int r = blockIdx.x, c = threadIdx.x;
    float v = (r < OUTD) ? W2[r * 256 + c] : 0.0f;
    __nv_bfloat16 h = __float2bfloat16(v);
    g_w2s[r * 512 + c]       = h;
    g_w2s[r * 512 + 256 + c] = __float2bfloat16(v - __bfloat162float(h));
}

// ---------------- cpart[b][g] = emb[concepts[b]] . Wih[g][512:1024] + bih[g] + bhh[g] --------
__global__ void k_cpart(const float* __restrict__ emb, const int* __restrict__ concepts,
                        const float* __restrict__ Wih, const float* __restrict__ bih,
                        const float* __restrict__ bhh) {
    int b = blockIdx.x >> 3;
    int g = ((blockIdx.x & 7) << 8) + threadIdx.x;
    const float4* e = (const float4*)(emb + (long)concepts[b] * HH);
    const float4* w = (const float4*)(Wih + (long)g * (2 * DD) + DD);
    float acc = bih[g] + bhh[g];
#pragma unroll 4
    for (int k = 0; k < HH / 4; k++) {
        float4 wv = __ldg(w + k);
        float4 ev = __ldg(e + k);
        acc += wv.x * ev.x + wv.y * ev.y + wv.z * ev.z + wv.w * ev.w;
    }
    g_cpart[b * G4 + g] = acc;
}

// ---------------- bf16-split tensor-core GEMM (mma.sync m16n8k16) ----------------
// C[M,N] = A[M,K] * B[N,:K]^T via Ah*Bh + Al*Bh + Ah*Bl over 3*(K/64) chunks from
// [hi|lo] arrays of row stride 2K. Tile 128x128, 8 warps 2m x 4n, warp 64x32.
// OSPLIT: write bf16 hi|lo into Cs (row stride 2N) instead of fp32 C.
template<int RELU, int PERM, int OSPLIT>
__global__ void __launch_bounds__(256, 2)
k_mma(const __nv_bfloat16* __restrict__ A, const __nv_bfloat16* __restrict__ B,
      const float* __restrict__ bias, const float* __restrict__ rowvec,
      float* __restrict__ C, __nv_bfloat16* __restrict__ Cs,
      int ldc, int N, int K) {
    __shared__ __nv_bfloat16 sA[128 * 72];
    __shared__ __nv_bfloat16 sB[128 * 72];
    int tid = threadIdx.x, wid = tid >> 5, lane = tid & 31;
    int wm = (wid >> 2) * 64, wn = (wid & 3) * 32;
    int ld2 = 2 * K, K2 = K >> 6;

    float d[4][4][4];
#pragma unroll
    for (int i = 0; i < 4; i++)
#pragma unroll
        for (int j = 0; j < 4; j++)
#pragma unroll
            for (int q = 0; q < 4; q++) d[i][j][q] = 0.0f;

    uint32_t sAu = s2u(sA), sBu = s2u(sB);
    uint32_t aRow = (uint32_t)(((wm + (lane & 15)) * 72 + (lane >> 4) * 8) * 2);
    uint32_t bRow = (uint32_t)(((wn + (lane >> 4) * 8 + (lane & 7)) * 72 + ((lane >> 3) & 1) * 8) * 2);

    long abase = (long)(blockIdx.y * 128) * ld2;
    long bbase = (long)(blockIdx.x * 128) * ld2;

    for (int term = 0; term < 3; term++)
    for (int qc = 0; qc < K2; qc++) {
        int ao = ((term == 1) ? K : 0) + qc * 64;
        int bo = ((term == 2) ? K : 0) + qc * 64;
#pragma unroll
        for (int it = 0; it < 4; it++) {
            int idx = tid + it * 256;
            int r = idx >> 3, cc = (idx & 7) * 8;
            *(uint4*)(sA + r * 72 + cc) = *(const uint4*)(A + abase + (long)r * ld2 + ao + cc);
            *(uint4*)(sB + r * 72 + cc) = *(const uint4*)(B + bbase + (long)r * ld2 + bo + cc);
        }
        __syncthreads();
#pragma unroll
        for (int ks = 0; ks < 4; ks++) {
            uint32_t af[4][4], bq[4], bf[4][2];
#pragma unroll
            for (int mi = 0; mi < 4; mi++)
                ldm_x4(af[mi], sAu + aRow + (uint32_t)((mi * 16 * 72 + ks * 16) * 2));
#pragma unroll
            for (int p = 0; p < 2; p++) {
                ldm_x4(bq, sBu + bRow + (uint32_t)((p * 16 * 72 + ks * 16) * 2));
                bf[p * 2][0]     = bq[0]; bf[p * 2][1]     = bq[1];
                bf[p * 2 + 1][0] = bq[2]; bf[p * 2 + 1][1] = bq[3];
            }
#pragma unroll
            for (int mi = 0; mi < 4; mi++)
#pragma unroll
                for (int nj = 0; nj < 4; nj++)
                    mma16816(d[mi][nj], af[mi], bf[nj][0], bf[nj][1]);
        }
        __syncthreads();
    }

    int g = lane >> 2, t2 = (lane & 3) * 2;
#pragma unroll
    for (int mi = 0; mi < 4; mi++) {
#pragma unroll
        for (int half = 0; half < 2; half++) {
            int mg = blockIdx.y * 128 + wm + mi * 16 + g + half * 8;
            const float* rv = rowvec ? (rowvec + (long)(mg >> 10) * N) : nullptr;
#pragma unroll
            for (int nj = 0; nj < 4; nj++) {
                int n = blockIdx.x * 128 + wn + nj * 8 + t2;
                float v0 = d[mi][nj][half * 2];
                float v1 = d[mi][nj][half * 2 + 1];
                if (bias) {
                    if (n < N)     v0 += bias[n];
                    if (n + 1 < N) v1 += bias[n + 1];
                }
                if (rv)   { v0 += rv[n];   v1 += rv[n + 1]; }
                if (RELU) { v0 = fmaxf(v0, 0.0f); v1 = fmaxf(v1, 0.0f); }
                if (OSPLIT) {
                    // hi|lo bf16 output, row stride 2N
                    __nv_bfloat162 lo;
                    __nv_bfloat162 hi = splt2(v0, v1, lo);
                    __nv_bfloat16* cr = Cs + (long)mg * (2 * N);
                    *(__nv_bfloat162*)(cr + n)     = hi;
                    *(__nv_bfloat162*)(cr + N + n) = lo;
                } else if (PERM) {
                    float* crow = C + (long)mg * ldc;
                    crow[(((n)     & 511) << 2) | ((n)     >> 9)] = v0;
                    crow[(((n + 1) & 511) << 2) | ((n + 1) >> 9)] = v1;
                } else {
                    float* crow = C + (long)mg * ldc;
                    if (n + 1 < N)      *(float2*)(crow + n) = make_float2(v0, v1);
                    else if (n < N)     crow[n] = v0;
                }
            }
        }
    }
}

// ---------------- persistent LSTM: 4 groups x 32 CTAs, fp32 f32x2 compute ----------------
// R11 structure + double-buffered partials: non-act warps skip the act barrier and
// run ahead into step t+1 (WAR on ps covered transitively by the flag protocol).
__global__ void __launch_bounds__(256, 1)
k_lstm(const float* __restrict__ pre, const float* __restrict__ Whh) {
    extern __shared__ float sm[];
    float* w_t = sm;                    // [512][64]  k-major weights
    float* h_s = w_t + 512 * 64;        // [512][8]   staged h (per-warp private slices)
    float* ps  = h_s + 512 * 8;         // [2][16][512] double-buffered partials
    float* c_s = ps + 2 * 16 * 512;     // [128]      cell state

    int tid   = threadIdx.x;
    int group = blockIdx.x >> 5;
    int gcta  = blockIdx.x & 31;
    int j0    = gcta * 16;
    int b0    = group * 8;
    int w     = tid >> 5;
    int lane  = tid & 31;

    for (int i = tid; i < 64 * 512; i += 256) {
        int lr = i & 63, k = i >> 6;
        int grow = ((lr >> 4) << 9) + j0 + (lr & 15);
        w_t[k * 64 + lr] = Whh[(long)grow * HH + k];
    }
    if (tid < 128) c_s[tid] = 0.0f;

    int ks  = tid >> 4;
    int l16 = tid & 15;
    int rt  = l16 >> 1;
    int bt  = l16 & 1;
    const float* wbase = w_t + (ks * 32) * 64 + rt * 8;
    const float* hbase = h_s + (ks * 32) * 8 + bt * 4;

    int jl = tid >> 3, ab = tid & 7;
    long preoff = (long)(b0 + ab) * LL * G4 + (j0 + jl) * 4;
    int slot_r = ((jl >> 1) & 3) ^ ((ab >> 2) << 1);
    int gb[4];
#pragma unroll
    for (int g = 0; g < 4; g++)
        gb[g] = g * 128 + ((jl >> 3) << 6) + ((ab >> 2) << 5) + slot_r * 8
              + ((ab & 3) << 1) + (jl & 1);

    float* hb_base = g_hbuf + group * 8192;
    unsigned* myflag = &g_flags[blockIdx.x * 32];
    const unsigned* pollflag = &g_flags[(group * 32 + w * 4 + (lane & 3)) * 32];

    __syncthreads();

    float4 pf4 = make_float4(0.f, 0.f, 0.f, 0.f);
    if (tid < 128) pf4 = *(const float4*)(pre + preoff);

    for (int t = 0; t < LL; t++) {
        float* psb = ps + (t & 1) * 8192;

        while (ld_acq(pollflag) < (unsigned)t) { }
        __syncwarp();
        {
            const float4* hin = (const float4*)(hb_base + (t & 1) * 4096) + w * 128;
            float4* hdst = (float4*)h_s + w * 128;
#pragma unroll
            for (int i = 0; i < 4; i++)
                hdst[lane + 32 * i] = __ldcg(hin + lane + 32 * i);
        }
        __syncwarp();

        unsigned long long acc[4][4];
#pragma unroll
        for (int rp = 0; rp < 4; rp++)
#pragma unroll
            for (int j = 0; j < 4; j++) acc[rp][j] = 0ull;

#pragma unroll 4
        for (int k = 0; k < 32; k++) {
            float4 wv0 = *(const float4*)(wbase + k * 64);
            float4 wv1 = *(const float4*)(wbase + k * 64 + 4);
            float4 hv  = *(const float4*)(hbase + k * 8);
            unsigned long long wp0 = pk2(wv0.x, wv0.y);
            unsigned long long wp1 = pk2(wv0.z, wv0.w);
            unsigned long long wp2 = pk2(wv1.x, wv1.y);
            unsigned long long wp3 = pk2(wv1.z, wv1.w);
            unsigned long long h0 = pk2(hv.x, hv.x);
            unsigned long long h1 = pk2(hv.y, hv.y);
            unsigned long long h2 = pk2(hv.z, hv.z);
            unsigned long long h3 = pk2(hv.w, hv.w);
            ffma2(acc[0][0], wp0, h0); ffma2(acc[0][1], wp0, h1);
            ffma2(acc[0][2], wp0, h2); ffma2(acc[0][3], wp0, h3);
            ffma2(acc[1][0], wp1, h0); ffma2(acc[1][1], wp1, h1);
            ffma2(acc[1][2], wp1, h2); ffma2(acc[1][3], wp1, h3);
            ffma2(acc[2][0], wp2, h0); ffma2(acc[2][1], wp2, h1);
            ffma2(acc[2][2], wp2, h2); ffma2(acc[2][3], wp2, h3);
            ffma2(acc[3][0], wp3, h0); ffma2(acc[3][1], wp3, h1);
            ffma2(acc[3][2], wp3, h2); ffma2(acc[3][3], wp3, h3);
        }
        {
            float* pp = psb + ks * 512 + l16 * 32;
#pragma unroll
            for (int rp = 0; rp < 4; rp++) {
                int slot = rp ^ (bt << 1);
                *(ulonglong2*)(pp + slot * 8)     = make_ulonglong2(acc[rp][0], acc[rp][1]);
                *(ulonglong2*)(pp + slot * 8 + 4) = make_ulonglong2(acc[rp][2], acc[rp][3]);
            }
        }
        __syncthreads();   // all partials of step t visible

        if (tid < 128) {
            float gs0 = 0.f, gs1 = 0.f, gs2 = 0.f, gs3 = 0.f;
#pragma unroll
            for (int kk = 0; kk < 16; kk++) {
                const float* pk = psb + kk * 512;
                gs0 += pk[gb[0]];
                gs1 += pk[gb[1]];
                gs2 += pk[gb[2]];
                gs3 += pk[gb[3]];
            }
            float gi = gs0 + pf4.x;
            float gf = gs1 + pf4.y;
            float gg = gs2 + pf4.z;
            float go = gs3 + pf4.w;
            float si = __fdividef(1.0f, 1.0f + __expf(-gi));
            float sf = __fdividef(1.0f, 1.0f + __expf(-gf));
            float so = __fdividef(1.0f, 1.0f + __expf(-go));
            float ag = fabsf(gg);
            float eg = __expf(-2.0f * ag);
            float tg = copysignf(__fdividef(1.0f - eg, 1.0f + eg), gg);
            float c  = sf * c_s[tid] + si * tg;
            c_s[tid] = c;
            float ac = fabsf(c);
            float ec = __expf(-2.0f * ac);
            float tc = copysignf(__fdividef(1.0f - ec, 1.0f + ec), c);
            float h  = so * tc;
            hb_base[((t + 1) & 1) * 4096 + (j0 + jl) * 8 + ab] = h;
            g_hout[((long)(b0 + ab) * LL + t) * HH + j0 + jl] = h;
            if (t + 1 < LL)
                pf4 = *(const float4*)(pre + preoff + (long)(t + 1) * G4);
            asm volatile("bar.sync 1, 128;" ::: "memory");
            if (tid == 0) st_rel(myflag, (unsigned)(t + 1));
        }
        // non-act warps fall through to t+1: their poll (flags >= t+1) transitively
        // guarantees act(t) completed group-wide before ps[(t+1)&1]'s next reuse.
    }
}

// ---------------- blocked cumsum ----------------
__global__ void k_csum1() {
    int c = blockIdx.x, b = blockIdx.y;
    int d = threadIdx.x;
    const float* s0 = g_hout + ((long)b * LL + c * 64) * HH + d;
    const float* s1 = s0 + 256;
    float* d0 = g_P + ((long)b * LL + c * 64) * HH + d;
    float* d1 = d0 + 256;
    float a0 = 0.f, a1 = 0.f;
#pragma unroll 8
    for (int t = 0; t < 64; t++) {
        a0 += s0[t * HH]; d0[t * HH] = a0;
        a1 += s1[t * HH]; d1[t * HH] = a1;
    }
    g_csum[((long)b * 16 + c) * HH + d]       = a0;
    g_csum[((long)b * 16 + c) * HH + d + 256] = a1;
}

__global__ void k_csum2() {
    int c = blockIdx.x + 1, b = blockIdx.y;
    int d = threadIdx.x;
    float o0 = 0.f, o1 = 0.f;
    for (int cc = 0; cc < c; cc++) {
        o0 += g_csum[((long)b * 16 + cc) * HH + d];
        o1 += g_csum[((long)b * 16 + cc) * HH + d + 256];
    }
    float* d0 = g_P + ((long)b * LL + c * 64) * HH + d;
    float* d1 = d0 + 256;
#pragma unroll 8
    for (int t = 0; t < 64; t++) {
        d0[t * HH] += o0;
        d1[t * HH] += o1;
    }
}

// ---------------- banded online-softmax attention (writes wgt as bf16 hi|lo) ------
__device__ __forceinline__ void upd(float& m, float& l, float4* acc, float sc, const float4* ov) {
    if (sc <= m) {
        float e = __expf(sc - m);
        l += e;
#pragma unroll
        for (int j = 0; j < 4; j++) {
            acc[j].x += e * ov[j].x; acc[j].y += e * ov[j].y;
            acc[j].z += e * ov[j].z; acc[j].w += e * ov[j].w;
        }
    } else {
        float coef = __expf(m - sc);
        l = l * coef + 1.0f;
#pragma unroll
        for (int j = 0; j < 4; j++) {
            acc[j].x = acc[j].x * coef + ov[j].x; acc[j].y = acc[j].y * coef + ov[j].y;
            acc[j].z = acc[j].z * coef + ov[j].z; acc[j].w = acc[j].w * coef + ov[j].w;
        }
        m = sc;
    }
}

__device__ __forceinline__ void store_wgt_split(__nv_bfloat16* base, int col,
                                                float4 r) {
    __nv_bfloat162 lo0, lo1;
    __nv_bfloat162 hi0 = splt2(r.x, r.y, lo0);
    __nv_bfloat162 hi1 = splt2(r.z, r.w, lo1);
    *(__nv_bfloat162*)(base + col)           = hi0;
    *(__nv_bfloat162*)(base + col + 2)       = hi1;
    *(__nv_bfloat162*)(base + 512 + col)     = lo0;
    *(__nv_bfloat162*)(base + 512 + col + 2) = lo1;
}

__global__ void k_attn() {
    int warp = (blockIdx.x * blockDim.x + threadIdx.x) >> 5;
    int lane = threadIdx.x & 31;
    int b  = warp >> 9;
    int tp = warp & 511;
    int t0 = tp * 2, t1 = t0 + 1;

    const float* mb = g_mlp  + (long)b * LL * DD;
    const float* ob = g_hout + (long)b * LL * HH;

    float4 q0[4], q1[4], acc0[4], acc1[4];
#pragma unroll
    for (int j = 0; j < 4; j++) {
        q0[j] = *(const float4*)(mb + (long)t0 * DD + lane * 4 + j * 128);
        q1[j] = *(const float4*)(mb + (long)t1 * DD + lane * 4 + j * 128);
        acc0[j] = make_float4(0.f, 0.f, 0.f, 0.f);
        acc1[j] = make_float4(0.f, 0.f, 0.f, 0.f);
    }
    float m0 = -1e30f, m1 = -1e30f, l0 = 0.0f, l1 = 0.0f;

    int slo = t0 - (WIN - 1); if (slo < 0) slo = 0;
    for (int s = slo; s <= t1; s++) {
        float4 ov[4];
        const float* op = ob + (long)s * HH + lane * 4;
#pragma unroll
        for (int j = 0; j < 4; j++) ov[j] = *(const float4*)(op + j * 128);
        float d0 = 0.f, d1 = 0.f;
#pragma unroll
        for (int j = 0; j < 4; j++) {
            d0 += q0[j].x * ov[j].x + q0[j].y * ov[j].y + q0[j].z * ov[j].z + q0[j].w * ov[j].w;
            d1 += q1[j].x * ov[j].x + q1[j].y * ov[j].y + q1[j].z * ov[j].z + q1[j].w * ov[j].w;
        }
#pragma unroll
        for (int off = 16; off; off >>= 1) {
            d0 += __shfl_xor_sync(0xFFFFFFFFu, d0, off);
            d1 += __shfl_xor_sync(0xFFFFFFFFu, d1, off);
        }
        if (s <= t0) {
            float sc = d0 * __expf(-0.6f * (float)(t0 - s));
            upd(m0, l0, acc0, sc, ov);
        }
        if (s >= t1 - (WIN - 1)) {
            float sc = d1 * __expf(-0.6f * (float)(t1 - s));
            upd(m1, l1, acc1, sc, ov);
        }
    }
    if (t0 >= WIN) {
        float cnt = (float)(t0 - (WIN - 1));
        const float* pp = g_P + ((long)b * LL + (t0 - WIN)) * HH + lane * 4;
        float4 pv[4];
#pragma unroll
        for (int j = 0; j < 4; j++) pv[j] = *(const float4*)(pp + j * 128);
        if (0.0f <= m0) {
            float e = __expf(-m0);
            l0 += cnt * e;
#pragma unroll
            for (int j = 0; j < 4; j++) {
                acc0[j].x += e * pv[j].x; acc0[j].y += e * pv[j].y;
                acc0[j].z += e * pv[j].z; acc0[j].w += e * pv[j].w;
            }
        } else {
            float coef = __expf(m0);
            l0 = l0 * coef + cnt;
#pragma unroll
            for (int j = 0; j < 4; j++) {
                acc0[j].x = acc0[j].x * coef + pv[j].x; acc0[j].y = acc0[j].y * coef + pv[j].y;
                acc0[j].z = acc0[j].z * coef + pv[j].z; acc0[j].w = acc0[j].w * coef + pv[j].w;
            }
            m0 = 0.0f;
        }
    }
    if (t1 >= WIN) {
        float cnt = (float)(t1 - (WIN - 1));
        const float* pp = g_P + ((long)b * LL + (t1 - WIN)) * HH + lane * 4;
        float4 pv[4];
#pragma unroll
        for (int j = 0; j < 4; j++) pv[j] = *(const float4*)(pp + j * 128);
        if (0.0f <= m1) {
            float e = __expf(-m1);
            l1 += cnt * e;
#pragma unroll
            for (int j = 0; j < 4; j++) {
                acc1[j].x += e * pv[j].x; acc1[j].y += e * pv[j].y;
                acc1[j].z += e * pv[j].z; acc1[j].w += e * pv[j].w;
            }
        } else {
            float coef = __expf(m1);
            l1 = l1 * coef + cnt;
#pragma unroll
            for (int j = 0; j < 4; j++) {
                acc1[j].x = acc1[j].x * coef + pv[j].x; acc1[j].y = acc1[j].y * coef + pv[j].y;
                acc1[j].z = acc1[j].z * coef + pv[j].z; acc1[j].w = acc1[j].w * coef + pv[j].w;
            }
            m1 = 0.0f;
        }
    }

    float inv0 = 1.0f / l0, inv1 = 1.0f / l1;
    __nv_bfloat16* w0 = g_wgts + ((long)b * LL + t0) * 1024;
    __nv_bfloat16* w1 = g_wgts + ((long)b * LL + t1) * 1024;
#pragma unroll
    for (int j = 0; j < 4; j++) {
        int col = lane * 4 + j * 128;
        float4 r0 = make_float4(acc0[j].x * inv0, acc0[j].y * inv0, acc0[j].z * inv0, acc0[j].w * inv0);
        float4 r1 = make_float4(acc1[j].x * inv1, acc1[j].y * inv1, acc1[j].z * inv1, acc1[j].w * inv1);
        store_wgt_split(w0, col, r0);
        store_wgt_split(w1, col, r1);
    }
}

// ---------------- launch ----------------
extern "C" void kernel_launch(void* const* d_in, const int* in_sizes, int n_in,
                              void* d_out, int out_size) {
    const float* x        = (const float*)d_in[0];
    const int*   concepts = (const int*)  d_in[1];
    const float* emb      = (const float*)d_in[2];
    const float* Wih      = (const float*)d_in[3];
    const float* Whh      = (const float*)d_in[4];
    const float* bih      = (const float*)d_in[5];
    const float* bhh      = (const float*)d_in[6];
    const float* Wm       = (const float*)d_in[7];
    const float* bm       = (const float*)d_in[8];
    const float* W1       = (const float*)d_in[9];
    const float* b1       = (const float*)d_in[10];
    const float* W2       = (const float*)d_in[11];
    const float* b2       = (const float*)d_in[12];
    float* out = (float*)d_out;

    float *p_pre, *p_cpart, *p_mlp;
    __nv_bfloat16 *p_xs, *p_wgts, *p_h1s, *p_wihs, *p_wms, *p_w1s, *p_w2s;
    cudaGetSymbolAddress((void**)&p_pre,   g_pre);
    cudaGetSymbolAddress((void**)&p_cpart, g_cpart);
    cudaGetSymbolAddress((void**)&p_mlp,   g_mlp);
    cudaGetSymbolAddress((void**)&p_xs,    g_xs);
    cudaGetSymbolAddress((void**)&p_wgts,  g_wgts);
    cudaGetSymbolAddress((void**)&p_h1s,   g_h1s);
    cudaGetSymbolAddress((void**)&p_wihs,  g_wihs);
    cudaGetSymbolAddress((void**)&p_wms,   g_wms);
    cudaGetSymbolAddress((void**)&p_w1s,   g_w1s);
    cudaGetSymbolAddress((void**)&p_w2s,   g_w2s);

    // smem: w_t 128KB + h_s 16KB + ps 64KB + c_s 512B = ~208.5KB
    const int lstm_smem = (512 * 64 + 512 * 8 + 2 * 16 * 512 + 128) * 4;
    cudaFuncSetAttribute(k_lstm, cudaFuncAttributeMaxDynamicSharedMemorySize, lstm_smem);

    const int M = BB * LL;   // 32768

    k_init<<<128, 256>>>();
    k_cpart<<<BB * 8, 256>>>(emb, concepts, Wih, bih, bhh);

    // bf16 hi|lo splits
    k_split<<<(int)(((long)M * DD) / 1024), 256>>>(x,   DD,     p_xs);
    k_split<<<(G4 * DD) / 1024,             256>>>(Wih, 2 * DD, p_wihs);   // WihA cols 0..511
    k_split<<<(DD * DD) / 1024,             256>>>(Wm,  DD,     p_wms);
    k_split<<<(FF * HH) / 1024,             256>>>(W1,  HH,     p_w1s);
    k_splitw2<<<128, 256>>>(W2);

    // pre = x @ WihA^T + cpart (PERMUTED output)
    k_mma<0, 1, 0><<<dim3(G4 / 128, M / 128), 256>>>(p_xs, p_wihs, nullptr, p_cpart,
                                                     p_pre, nullptr, G4, G4, DD);
    // mlp = x @ Wm^T + bm
    k_mma<0, 0, 0><<<dim3(DD / 128, M / 128), 256>>>(p_xs, p_wms, bm, nullptr,
                                                     p_mlp, nullptr, DD, DD, DD);

    // LSTM recurrence (4 groups x 32 CTAs)
    k_lstm<<<NCTA_LSTM, 256, lstm_smem>>>(p_pre, Whh);

    // blocked prefix sums
    k_csum1<<<dim3(16, BB), 256>>>();
    k_csum2<<<dim3(15, BB), 256>>>();

    // attention (emits wgt directly as bf16 hi|lo)
    k_attn<<<2048, 256>>>();

    // h1 = relu(wgt @ W1^T + b1) -> bf16 hi|lo (OSPLIT)
    k_mma<1, 0, 1><<<dim3(FF / 128, M / 128), 256>>>(p_wgts, p_w1s, b1, nullptr,
                                                     nullptr, p_h1s, FF, FF, HH);
    // res = h1 @ W2^T + b2 (K=256, N=100 in one padded 128-tile)
    k_mma<0, 0, 0><<<dim3(1, M / 128), 256>>>(p_h1s, p_w2s, b2, nullptr,
                                              out, nullptr, OUTD, OUTD, FF);
}